// round 4
// baseline (speedup 1.0000x reference)
#include <cuda_runtime.h>
#include <cstdint>

// ---------------------------------------------------------------------------
// Fused Reading_memory, R4: batch-pair interleaved smem layout.
// Resident arrays stored [pair][q][k][b] so one LDS.128 feeds both batches;
// f32x2 accumulators packed over the batch pair; W broadcast + dup by MOV.
// NB=10 batches/CTA, 128 threads, ~98.6KB smem -> 2 CTAs/SM.
// ---------------------------------------------------------------------------

typedef unsigned long long ull;

#define NB 10
#define NP 5            // batch pairs per CTA
#define TQ 25           // column quads
#define KC 50           // k-chunk
#define THREADS 128

struct __align__(16) SM {
    float se[NB * 500];   // interleaved: p*1000 + q*200 + k*2 + b
    float rs[NB * 500];   // raw -> s4
    float ms[NB * 500];   // memory -> sub_mem
    float m4[NB * 500];   // mem_4att
    float ws[KC * 100];   // weight chunk (natural [k][n])
    float att[NP * 50];   // p*50 + q*10 + kv*2 + b
};
#define SMEM_BYTES ((int)sizeof(SM))

__device__ __forceinline__ ull fma2(ull a, ull b, ull c) {
    ull d;
    asm("fma.rn.f32x2 %0, %1, %2, %3;" : "=l"(d) : "l"(a), "l"(b), "l"(c));
    return d;
}
__device__ __forceinline__ ull mul2(ull a, ull b) {
    ull d;
    asm("mul.rn.f32x2 %0, %1, %2;" : "=l"(d) : "l"(a), "l"(b));
    return d;
}
__device__ __forceinline__ ull pack2(float lo, float hi) {
    ull r;
    asm("mov.b64 %0, {%1, %2};" : "=l"(r) : "r"(__float_as_uint(lo)), "r"(__float_as_uint(hi)));
    return r;
}
__device__ __forceinline__ float2 unpack2(ull v) {
    unsigned int lo, hi;
    asm("mov.b64 {%0, %1}, %2;" : "=r"(lo), "=r"(hi) : "l"(v));
    float2 r; r.x = __uint_as_float(lo); r.y = __uint_as_float(hi);
    return r;
}
__device__ __forceinline__ float sigf(float x) { return 1.0f / (1.0f + __expf(-x)); }

__device__ __forceinline__ void cpa16(void* dst_smem, const void* src) {
    unsigned saddr = (unsigned)__cvta_generic_to_shared(dst_smem);
    asm volatile("cp.async.cg.shared.global [%0], [%1], 16;" :: "r"(saddr), "l"(src));
}
__device__ __forceinline__ void cpa_commit_wait() {
    asm volatile("cp.async.commit_group;");
    asm volatile("cp.async.wait_group 0;" ::: "memory");
}

// ---- core MMA over one 50-k chunk, batch-packed accumulators ----
// xpair points at interleaved x for this pair & chunk: [q*200 + 2k + b]
template <bool PROD>
__device__ __forceinline__ void mm(const float* __restrict__ xpair,
                                   const float* __restrict__ ppair,
                                   const float* __restrict__ ws,
                                   ull a[5][4], int c0)
{
#pragma unroll
    for (int i = 0; i < KC / 2; i++) {
        const int k = 2 * i;
        float4 w0 = *(const float4*)&ws[k * 100 + c0];
        float4 w1 = *(const float4*)&ws[k * 100 + 100 + c0];
        ull w0d0 = pack2(w0.x, w0.x), w0d1 = pack2(w0.y, w0.y);
        ull w0d2 = pack2(w0.z, w0.z), w0d3 = pack2(w0.w, w0.w);
        ull w1d0 = pack2(w1.x, w1.x), w1d1 = pack2(w1.y, w1.y);
        ull w1d2 = pack2(w1.z, w1.z), w1d3 = pack2(w1.w, w1.w);
#pragma unroll
        for (int q = 0; q < 5; q++) {
            ulonglong2 xv = *(const ulonglong2*)&xpair[q * 200 + 2 * k];
            if (PROD) {
                ulonglong2 pv = *(const ulonglong2*)&ppair[q * 200 + 2 * k];
                xv.x = mul2(xv.x, pv.x);
                xv.y = mul2(xv.y, pv.y);
            }
            a[q][0] = fma2(xv.x, w0d0, a[q][0]);
            a[q][1] = fma2(xv.x, w0d1, a[q][1]);
            a[q][2] = fma2(xv.x, w0d2, a[q][2]);
            a[q][3] = fma2(xv.x, w0d3, a[q][3]);
            a[q][0] = fma2(xv.y, w1d0, a[q][0]);
            a[q][1] = fma2(xv.y, w1d1, a[q][1]);
            a[q][2] = fma2(xv.y, w1d2, a[q][2]);
            a[q][3] = fma2(xv.y, w1d3, a[q][3]);
        }
    }
}

// ---- one GEMM stage ----
template <int MODE>
__device__ __forceinline__ void gemm_stage(SM* s,
                                           const float* __restrict__ W,
                                           const float* __restrict__ bias,
                                           float* __restrict__ dout,
                                           int b0, int B)
{
    constexpr int NC = (MODE == 0) ? 2 : (MODE == 1 ? 4 : 6);
    const int tid = threadIdx.x;
    const bool act = tid < NP * TQ;
    const int p = tid / TQ;
    const int t = tid - p * TQ;
    const int c0 = 4 * t;

    ull a[5][4];
    {
        ull bd[4] = {0, 0, 0, 0};
        if (act) {
            float4 bv = *(const float4*)&bias[c0];
            bd[0] = pack2(bv.x, bv.x); bd[1] = pack2(bv.y, bv.y);
            bd[2] = pack2(bv.z, bv.z); bd[3] = pack2(bv.w, bv.w);
        }
#pragma unroll
        for (int q = 0; q < 5; q++)
#pragma unroll
            for (int j = 0; j < 4; j++) a[q][j] = bd[j];
    }

    for (int c = 0; c < NC; c++) {
        __syncthreads();            // prior math done reading ws
        {
            const float4* wsrc = (const float4*)(W + c * KC * 100);
#pragma unroll
            for (int i = 0; i < 10; i++) {
                int idx = tid + i * THREADS;
                if (idx < 1250) cpa16(&s->ws[idx * 4], wsrc + idx);
            }
            cpa_commit_wait();
        }
        __syncthreads();

        if (act) {
            const int xoff = p * 1000 + (c & 1) * KC * 2;
            if (MODE == 0) {
                mm<false>(s->ms + xoff, nullptr, s->ws, a, c0);
            } else if (MODE == 1) {
                mm<false>((c < 2 ? s->se : s->rs) + xoff, nullptr, s->ws, a, c0);
            } else {
                if (c < 2)      mm<false>(s->se + xoff, nullptr, s->ws, a, c0);
                else if (c < 4) mm<false>(s->ms + xoff, nullptr, s->ws, a, c0);
                else            mm<true>(s->se + xoff, s->ms + xoff, s->ws, a, c0);
            }
        }
    }

    if (MODE < 2) __syncthreads();  // all reads done before overwriting dst (MODE1: rs)

    if (act) {
#pragma unroll
        for (int q = 0; q < 5; q++) {
            if (MODE < 2) {
                // tanh each lane of the packed pairs, store interleaved
#pragma unroll
                for (int j = 0; j < 4; j++) {
                    float2 v = unpack2(a[q][j]);
                    a[q][j] = pack2(tanhf(v.x), tanhf(v.y));
                }
                float* dst = (MODE == 0) ? s->m4 : s->rs;
                ulonglong2 s01; s01.x = a[q][0]; s01.y = a[q][1];
                ulonglong2 s23; s23.x = a[q][2]; s23.y = a[q][3];
                *(ulonglong2*)&dst[p * 1000 + q * 200 + 2 * c0]     = s01;
                *(ulonglong2*)&dst[p * 1000 + q * 200 + 2 * c0 + 4] = s23;
            } else {
                ulonglong2 se01 = *(const ulonglong2*)&s->se[p * 1000 + q * 200 + 2 * c0];
                ulonglong2 se23 = *(const ulonglong2*)&s->se[p * 1000 + q * 200 + 2 * c0 + 4];
                ulonglong2 sm01 = *(const ulonglong2*)&s->ms[p * 1000 + q * 200 + 2 * c0];
                ulonglong2 sm23 = *(const ulonglong2*)&s->ms[p * 1000 + q * 200 + 2 * c0 + 4];
                ull sev[4] = {se01.x, se01.y, se23.x, se23.y};
                ull smv[4] = {sm01.x, sm01.y, sm23.x, sm23.y};
                float4 o0, o1;
                float* o0p = &o0.x; float* o1p = &o1.x;
#pragma unroll
                for (int j = 0; j < 4; j++) {
                    float2 gv = unpack2(a[q][j]);
                    float2 sep = unpack2(sev[j]);
                    float2 smp = unpack2(smv[j]);
                    o0p[j] = fmaf(sigf(gv.x), smp.x - sep.x, sep.x);
                    o1p[j] = fmaf(sigf(gv.y), smp.y - sep.y, sep.y);
                }
                const int gb0 = b0 + 2 * p;
                if (gb0 < B)     *(float4*)&dout[gb0 * 500 + q * 100 + c0] = o0;
                if (gb0 + 1 < B) *(float4*)&dout[(gb0 + 1) * 500 + q * 100 + c0] = o1;
            }
        }
    }
}

// ---------------------------------------------------------------------------
__global__ __launch_bounds__(THREADS, 2)
void fused_kernel(const float* __restrict__ sub_emb,
                  const float* __restrict__ memory,
                  const int*   __restrict__ sub_len,
                  const float* __restrict__ raw,
                  const float* __restrict__ W_mem,  const float* __restrict__ b_mem,
                  const float* __restrict__ W_sub,  const float* __restrict__ b_sub,
                  const float* __restrict__ W_gate, const float* __restrict__ b_gate,
                  float* __restrict__ dout, int B)
{
    extern __shared__ __align__(16) char smraw[];
    SM* s = (SM*)smraw;
    const int tid = threadIdx.x;
    const int b0 = blockIdx.x * NB;

    // ---- stage inputs, interleaving batch pairs on the fly ----
    {
        const float4 z4 = make_float4(0.f, 0.f, 0.f, 0.f);
#pragma unroll
        for (int ii = 0; ii < 5; ii++) {
            int idx = tid + ii * THREADS;       // [0, 625): pair x float4-row
            if (idx < NP * 125) {
                int p = idx / 125, r = idx - p * 125;
                int h = 4 * r, q = h / 100, k = h - q * 100;
                int gb0 = b0 + 2 * p;
                const int goff0 = gb0 * 500 + h;
                const int goff1 = goff0 + 500;
                const int soff = p * 1000 + q * 200 + 2 * k;
#pragma unroll
                for (int arr = 0; arr < 3; arr++) {
                    const float* src = (arr == 0) ? sub_emb : (arr == 1) ? raw : memory;
                    float* dst = (arr == 0) ? s->se : (arr == 1) ? s->rs : s->ms;
                    float4 v0 = (gb0 < B)     ? *(const float4*)&src[goff0] : z4;
                    float4 v1 = (gb0 + 1 < B) ? *(const float4*)&src[goff1] : z4;
                    float4 w0; w0.x = v0.x; w0.y = v1.x; w0.z = v0.y; w0.w = v1.y;
                    float4 w1; w1.x = v0.z; w1.y = v1.z; w1.z = v0.w; w1.w = v1.w;
                    *(float4*)&dst[soff]     = w0;
                    *(float4*)&dst[soff + 4] = w1;
                }
            }
        }
    }
    // gemm_stage starts with __syncthreads before touching ws

    gemm_stage<0>(s, W_mem, b_mem, nullptr, b0, B);   // -> m4
    gemm_stage<1>(s, W_sub, b_sub, nullptr, b0, B);   // -> rs(=s4)
    __syncthreads();                                  // m4/s4 visible

    // ---- attention scores for both batches of the pair at once ----
    if (tid < NP * TQ) {
        const int p = tid / TQ;
        const int qk = tid - p * TQ;
        const int q = qk / 5, kv = qk - 5 * q;
        const float* sp = &s->rs[p * 1000 + q * 200];
        const float* mp = &s->m4[p * 1000 + kv * 200];
        ull acc = 0ull;
#pragma unroll
        for (int j = 0; j < 50; j++) {
            ulonglong2 sv = *(const ulonglong2*)&sp[4 * j];
            ulonglong2 mv = *(const ulonglong2*)&mp[4 * j];
            acc = fma2(sv.x, mv.x, acc);
            acc = fma2(sv.y, mv.y, acc);
        }
        *(ull*)&s->att[p * 50 + q * 10 + kv * 2] = acc;   // (dot_b0, dot_b1)
    }
    __syncthreads();

    // ---- softmax per (b,q) with length mask ----
    if (tid < NB * 5) {
        const int bl = tid / 5, q = tid - 5 * bl;
        const int p = bl >> 1, bb = bl & 1;
        const int gb = b0 + bl;
        const int len = (gb < B) ? sub_len[gb] : 5;
        float v[5];
#pragma unroll
        for (int kv = 0; kv < 5; kv++) v[kv] = s->att[p * 50 + q * 10 + kv * 2 + bb];
        float m = v[0];
#pragma unroll
        for (int kv = 1; kv < 5; kv++) m = fmaxf(m, v[kv]);
        float e[5], smv = 0.f;
#pragma unroll
        for (int kv = 0; kv < 5; kv++) { e[kv] = __expf(v[kv] - m); smv += e[kv]; }
        const float inv = (q < len) ? (1.0f / smv) : 0.0f;
#pragma unroll
        for (int kv = 0; kv < 5; kv++) s->att[p * 50 + q * 10 + kv * 2 + bb] = e[kv] * inv;
    }
    __syncthreads();

    // ---- sub_mem = att @ memory (packed over batch pair; overwrites ms) ----
    if (tid < NP * TQ) {
        const int p = tid / TQ;
        const int t = tid - p * TQ;
        const int c0 = 4 * t;
        ull av[25];
#pragma unroll
        for (int j = 0; j < 25; j++) av[j] = *(const ull*)&s->att[p * 50 + 2 * j];
        ull c2[5][4];
#pragma unroll
        for (int q = 0; q < 5; q++)
#pragma unroll
            for (int j = 0; j < 4; j++) c2[q][j] = 0ull;
#pragma unroll
        for (int kv = 0; kv < 5; kv++) {
            ulonglong2 m01 = *(const ulonglong2*)&s->ms[p * 1000 + kv * 200 + 2 * c0];
            ulonglong2 m23 = *(const ulonglong2*)&s->ms[p * 1000 + kv * 200 + 2 * c0 + 4];
#pragma unroll
            for (int q = 0; q < 5; q++) {
                ull ap = av[q * 5 + kv];
                c2[q][0] = fma2(ap, m01.x, c2[q][0]);
                c2[q][1] = fma2(ap, m01.y, c2[q][1]);
                c2[q][2] = fma2(ap, m23.x, c2[q][2]);
                c2[q][3] = fma2(ap, m23.y, c2[q][3]);
            }
        }
#pragma unroll
        for (int q = 0; q < 5; q++) {
            ulonglong2 s01; s01.x = c2[q][0]; s01.y = c2[q][1];
            ulonglong2 s23; s23.x = c2[q][2]; s23.y = c2[q][3];
            *(ulonglong2*)&s->ms[p * 1000 + q * 200 + 2 * c0]     = s01;
            *(ulonglong2*)&s->ms[p * 1000 + q * 200 + 2 * c0 + 4] = s23;
        }
    }
    // gemm_stage<2> begins with __syncthreads (orders ms writes before reads)

    gemm_stage<2>(s, W_gate, b_gate, dout, b0, B);    // -> gmem out
}

// ---------------------------------------------------------------------------
extern "C" void kernel_launch(void* const* d_in, const int* in_sizes, int n_in,
                              void* d_out, int out_size)
{
    const float* sub_emb = (const float*)d_in[0];
    const float* memory  = (const float*)d_in[1];
    const int*   sub_len = (const int*)d_in[2];
    const float* raw     = (const float*)d_in[3];
    const float* W_mem   = (const float*)d_in[4];
    const float* b_mem   = (const float*)d_in[5];
    const float* W_sub   = (const float*)d_in[6];
    const float* b_sub   = (const float*)d_in[7];
    const float* W_gate  = (const float*)d_in[8];
    const float* b_gate  = (const float*)d_in[9];
    float* out = (float*)d_out;
    const int B = in_sizes[2];

    cudaFuncSetAttribute(fused_kernel, cudaFuncAttributeMaxDynamicSharedMemorySize, SMEM_BYTES);
    const int nc = (B + NB - 1) / NB;
    fused_kernel<<<nc, THREADS, SMEM_BYTES>>>(sub_emb, memory, sub_len, raw,
                                              W_mem, b_mem, W_sub, b_sub,
                                              W_gate, b_gate, out, B);
}

// round 6
// speedup vs baseline: 1.2069x; 1.2069x over previous
#include <cuda_runtime.h>
#include <cuda_bf16.h>
#include <cstdint>

// ---------------------------------------------------------------------------
// Reading_memory R6: warp-level mma.sync bf16x3 GEMMs (tensor pipe, no tcgen05)
//   rows = B*5 flattened.  Y = act(X @ W + b), N=100 (pad 104), K in {100,200,300}
//     stage0: X=memory                -> g_m4 (tanh)
//     stage1: X=cat(se,raw)           -> g_s4 (tanh)
//     attn  : softmax(s4 m4^T) masked; g_sm = att @ memory
//     stage2: X=cat(se,sm,se*sm)      -> out (sigmoid gate blend)
//   bf16 split x = xh + xl; acc += Ah*Bh + Ah*Bl + Al*Bh  (fp32 regs)
// ---------------------------------------------------------------------------

#define B_MAX 65536
#define HID 100
#define MT   128          // rows per CTA
#define KCH  64           // k per chunk
#define AST  72           // padded k-stride (elems) -> 144B rows, LDSM bank-safe
typedef unsigned long long ull;
typedef unsigned int uint;

__device__ __align__(16) static float g_m4[B_MAX * 500];
__device__ __align__(16) static float g_s4[B_MAX * 500];
__device__ __align__(16) static float g_sm[B_MAX * 500];
// weight images: [stagechunk 11][split hi/lo][n(104) * AST]  (bf16, k-padded)
__device__ __align__(16) static __nv_bfloat16 g_Bimg[11][2][104 * AST];

__device__ __forceinline__ float sigf(float x) { return 1.0f / (1.0f + __expf(-x)); }

__device__ __forceinline__ ull fma2(ull a, ull b, ull c) {
    ull d;
    asm("fma.rn.f32x2 %0, %1, %2, %3;" : "=l"(d) : "l"(a), "l"(b), "l"(c));
    return d;
}
__device__ __forceinline__ ull pack2(float lo, float hi) {
    ull r;
    asm("mov.b64 %0, {%1, %2};" : "=l"(r) : "r"(__float_as_uint(lo)), "r"(__float_as_uint(hi)));
    return r;
}
__device__ __forceinline__ float2 unpack2(ull v) {
    uint lo, hi;
    asm("mov.b64 {%0, %1}, %2;" : "=r"(lo), "=r"(hi) : "l"(v));
    float2 r; r.x = __uint_as_float(lo); r.y = __uint_as_float(hi);
    return r;
}

__device__ __forceinline__ void splitpack(float x, float y, uint& hi, uint& lo) {
    __nv_bfloat16 hx = __float2bfloat16(x), hy = __float2bfloat16(y);
    float rx = x - __bfloat162float(hx);
    float ry = y - __bfloat162float(hy);
    __nv_bfloat16 lx = __float2bfloat16(rx), ly = __float2bfloat16(ry);
    hi = ((uint)__bfloat16_as_ushort(hy) << 16) | __bfloat16_as_ushort(hx);
    lo = ((uint)__bfloat16_as_ushort(ly) << 16) | __bfloat16_as_ushort(lx);
}

#define LDSM4(d0, d1, d2, d3, addr) \
    asm volatile("ldmatrix.sync.aligned.m8n8.x4.shared.b16 {%0,%1,%2,%3}, [%4];" \
                 : "=r"(d0), "=r"(d1), "=r"(d2), "=r"(d3) : "r"(addr))
#define LDSM2(d0, d1, addr) \
    asm volatile("ldmatrix.sync.aligned.m8n8.x2.shared.b16 {%0,%1}, [%2];" \
                 : "=r"(d0), "=r"(d1) : "r"(addr))

__device__ __forceinline__ void mma16816(float c[4], uint a0, uint a1, uint a2, uint a3,
                                         uint b0, uint b1) {
    asm volatile(
        "mma.sync.aligned.m16n8k16.row.col.f32.bf16.bf16.f32 "
        "{%0,%1,%2,%3}, {%4,%5,%6,%7}, {%8,%9}, {%0,%1,%2,%3};"
        : "+f"(c[0]), "+f"(c[1]), "+f"(c[2]), "+f"(c[3])
        : "r"(a0), "r"(a1), "r"(a2), "r"(a3), "r"(b0), "r"(b1));
}

// ---------------------------------------------------------------------------
// prep: transposed/split/padded weight images. img[n*AST + k] = W[gk][n]
// stagechunk: 0-1 = W_mem, 2-5 = W_sub, 6-10 = W_gate
// ---------------------------------------------------------------------------
__global__ void prep_kernel(const float* __restrict__ Wm,
                            const float* __restrict__ Ws,
                            const float* __restrict__ Wg)
{
    const int idx = blockIdx.x * blockDim.x + threadIdx.x;
    const int PER = 104 * KCH;
    if (idx >= 11 * PER) return;
    const int cidx = idx / PER;
    const int rem = idx - cidx * PER;
    const int n = rem / KCH, k = rem - n * KCH;
    int c, KS;
    const float* W;
    if (cidx < 2)      { W = Wm; c = cidx;     KS = 100; }
    else if (cidx < 6) { W = Ws; c = cidx - 2; KS = 200; }
    else               { W = Wg; c = cidx - 6; KS = 300; }
    const int gk = c * KCH + k;
    float v = (n < HID && gk < KS) ? W[gk * HID + n] : 0.0f;
    __nv_bfloat16 hi = __float2bfloat16(v);
    __nv_bfloat16 lo = __float2bfloat16(v - __bfloat162float(hi));
    g_Bimg[cidx][0][n * AST + k] = hi;
    g_Bimg[cidx][1][n * AST + k] = lo;
}

// ---------------------------------------------------------------------------
// GEMM: 256 threads, 8 warps; warp w owns rows [w*16, w*16+16) of the 128-tile
// and all 13 n-tiles. SMEM (bytes):
//   AH 0..18431, AL 18432..36863  (128 x AST bf16 each)
//   BH 36864..51839, BL 51840..66815 (104 x AST bf16 each)
//   BIAS 66816..67231
// ---------------------------------------------------------------------------
#define OFF_AH 0
#define OFF_AL 18432
#define OFF_BH 36864
#define OFF_BL 51840
#define OFF_BIAS 66816
#define GSMEM 67232

template <int STAGE>
__global__ __launch_bounds__(256)
void gemm_tc(const float* __restrict__ se,
             const float* __restrict__ mem,
             const float* __restrict__ raw,
             const float* __restrict__ bias,
             float* __restrict__ dout,
             int rows)
{
    constexpr int NC = (STAGE == 0) ? 2 : (STAGE == 1 ? 4 : 5);
    constexpr int KS = (STAGE == 0) ? 100 : (STAGE == 1 ? 200 : 300);
    constexpr int CBASE = (STAGE == 0) ? 0 : (STAGE == 1 ? 2 : 6);
    extern __shared__ __align__(16) char smc[];
    float* bias_s = (float*)(smc + OFF_BIAS);
    const uint smb = (uint)__cvta_generic_to_shared(smc);
    const int tid = threadIdx.x;
    const int wid = tid >> 5;
    const int lane = tid & 31;
    const int row0 = blockIdx.x * MT;

    if (tid < 104) bias_s[tid] = (tid < HID) ? bias[tid] : 0.0f;

    float acc[13][4];
#pragma unroll
    for (int nt = 0; nt < 13; nt++)
#pragma unroll
        for (int j = 0; j < 4; j++) acc[nt][j] = 0.0f;

    // per-lane ldmatrix base addresses
    const uint aoff = (uint)(((lane & 15) * AST + (lane >> 4) * 8) * 2);
    const uint aH = smb + OFF_AH + (uint)(wid * 16 * AST * 2) + aoff;
    const uint aL = smb + OFF_AL + (uint)(wid * 16 * AST * 2) + aoff;
    const uint boff = (uint)(((lane & 7) * AST + ((lane >> 3) & 1) * 8) * 2);
    const uint bH = smb + OFF_BH + boff;
    const uint bL = smb + OFF_BL + boff;

    for (int c = 0; c < NC; c++) {
        __syncthreads();            // previous chunk's math done with smem
        // ---- build A chunk (bf16 split): 128 rows x 16 k-quads ----
#pragma unroll
        for (int it = 0; it < 8; it++) {
            const int idx = tid + it * 256;        // [0,2048)
            const int r = idx >> 4, kq = idx & 15;
            const int grow = row0 + r;
            const int k = c * KCH + kq * 4;
            float4 v = make_float4(0.f, 0.f, 0.f, 0.f);
            if (grow < rows && k < KS) {
                if (STAGE == 0) {
                    v = *(const float4*)&mem[grow * HID + k];
                } else if (STAGE == 1) {
                    v = (k < HID) ? *(const float4*)&se[grow * HID + k]
                                  : *(const float4*)&raw[grow * HID + k - HID];
                } else {
                    if (k < HID) {
                        v = *(const float4*)&se[grow * HID + k];
                    } else if (k < 2 * HID) {
                        v = *(const float4*)&g_sm[grow * HID + k - HID];
                    } else {
                        float4 a4 = *(const float4*)&se[grow * HID + k - 2 * HID];
                        float4 b4 = *(const float4*)&g_sm[grow * HID + k - 2 * HID];
                        v.x = a4.x * b4.x; v.y = a4.y * b4.y;
                        v.z = a4.z * b4.z; v.w = a4.w * b4.w;
                    }
                }
            }
            uint h01, l01, h23, l23;
            splitpack(v.x, v.y, h01, l01);
            splitpack(v.z, v.w, h23, l23);
            const int sb = (r * AST + kq * 4) * 2;   // byte offset
            *(uint2*)(smc + OFF_AH + sb) = make_uint2(h01, h23);
            *(uint2*)(smc + OFF_AL + sb) = make_uint2(l01, l23);
        }
        // ---- copy B chunk images (contiguous) ----
        {
            const uint4* bh = (const uint4*)&g_Bimg[CBASE + c][0][0];
            const uint4* bl = (const uint4*)&g_Bimg[CBASE + c][1][0];
#pragma unroll
            for (int it = 0; it < 4; it++) {
                int idx = tid + it * 256;
                if (idx < (104 * AST * 2) / 16) {
                    ((uint4*)(smc + OFF_BH))[idx] = bh[idx];
                    ((uint4*)(smc + OFF_BL))[idx] = bl[idx];
                }
            }
        }
        __syncthreads();

        // ---- compute: 4 k-steps x 13 n-tiles x 3 split passes ----
#pragma unroll
        for (int ks = 0; ks < 4; ks++) {
            const uint k2 = (uint)(ks * 32);       // k0 * 2 bytes
            uint ah0, ah1, ah2, ah3, al0, al1, al2, al3;
            LDSM4(ah0, ah1, ah2, ah3, aH + k2);
            LDSM4(al0, al1, al2, al3, aL + k2);
#pragma unroll
            for (int nt = 0; nt < 13; nt++) {
                uint bh0, bh1, bl0, bl1;
                LDSM2(bh0, bh1, bH + (uint)(nt * 8 * AST * 2) + k2);
                LDSM2(bl0, bl1, bL + (uint)(nt * 8 * AST * 2) + k2);
                mma16816(acc[nt], ah0, ah1, ah2, ah3, bh0, bh1);
                mma16816(acc[nt], ah0, ah1, ah2, ah3, bl0, bl1);
                mma16816(acc[nt], al0, al1, al2, al3, bh0, bh1);
            }
        }
    }

    // ---- epilogue ----
    const int g = lane >> 2, tg = lane & 3;
    const int r0 = row0 + wid * 16 + g;
    const int r1 = r0 + 8;
#pragma unroll
    for (int nt = 0; nt < 13; nt++) {
        const int n0 = nt * 8 + tg * 2;
        if (n0 >= HID) continue;
        const float bz0 = bias_s[n0], bz1 = bias_s[n0 + 1];
#pragma unroll
        for (int half = 0; half < 2; half++) {
            const int rr = half ? r1 : r0;
            if (rr >= rows) continue;
            float z0 = acc[nt][half * 2]     + bz0;
            float z1 = acc[nt][half * 2 + 1] + bz1;
            const int off = rr * HID + n0;
            float2 o;
            if (STAGE < 2) {
                o.x = tanhf(z0); o.y = tanhf(z1);
                float* dst = (STAGE == 0) ? g_m4 : g_s4;
                *(float2*)&dst[off] = o;
            } else {
                float2 sev = *(const float2*)&se[off];
                float2 smv = *(const float2*)&g_sm[off];
                o.x = fmaf(sigf(z0), smv.x - sev.x, sev.x);
                o.y = fmaf(sigf(z1), smv.y - sev.y, sev.y);
                *(float2*)&dout[off] = o;
            }
        }
    }
}

// ---------------------------------------------------------------------------
// Attention kernel (known-good): one warp per batch, 8 per CTA.
// ---------------------------------------------------------------------------
__global__ __launch_bounds__(256)
void attn_kernel(const float* __restrict__ memory,
                 const int* __restrict__ sub_len,
                 int B)
{
    __shared__ __align__(16) float s4s[8][500];
    __shared__ __align__(16) float m4s[8][500];
    __shared__ float atts[8][25];
    __shared__ __align__(16) ull attd[8][25];

    const int w = threadIdx.x >> 5;
    const int lane = threadIdx.x & 31;
    const int b = blockIdx.x * 8 + w;
    if (b >= B) return;

    for (int i = lane; i < 125; i += 32) {
        *(float4*)&s4s[w][4 * i] = *(const float4*)&g_s4[b * 500 + 4 * i];
        *(float4*)&m4s[w][4 * i] = *(const float4*)&g_m4[b * 500 + 4 * i];
    }
    __syncwarp();

    if (lane < 25) {
        const int q = lane / 5, kk = lane % 5;
        float a = 0.0f;
#pragma unroll 4
        for (int h = 0; h < 100; h++)
            a += s4s[w][q * 100 + h] * m4s[w][kk * 100 + h];
        atts[w][lane] = a;
    }
    __syncwarp();

    if (lane < 5) {
        const int q = lane;
        const int len = sub_len[b];
        float a[5];
#pragma unroll
        for (int i = 0; i < 5; i++) a[i] = atts[w][q * 5 + i];
        float m = a[0];
#pragma unroll
        for (int i = 1; i < 5; i++) m = fmaxf(m, a[i]);
        float e[5], s = 0.0f;
#pragma unroll
        for (int i = 0; i < 5; i++) { e[i] = __expf(a[i] - m); s += e[i]; }
        const float inv = (q < len) ? (1.0f / s) : 0.0f;
#pragma unroll
        for (int i = 0; i < 5; i++) {
            float r = e[i] * inv;
            attd[w][q * 5 + i] = pack2(r, r);
        }
    }
    __syncwarp();

    if (lane < 25) {
        const int c0 = 4 * lane;
        ull acc[5][2];
#pragma unroll
        for (int q = 0; q < 5; q++) { acc[q][0] = 0ull; acc[q][1] = 0ull; }
#pragma unroll
        for (int kk = 0; kk < 5; kk++) {
            ulonglong2 mv = *(const ulonglong2*)&memory[b * 500 + kk * 100 + c0];
#pragma unroll
            for (int q = 0; q < 5; q++) {
                ull ad = attd[w][q * 5 + kk];
                acc[q][0] = fma2(ad, mv.x, acc[q][0]);
                acc[q][1] = fma2(ad, mv.y, acc[q][1]);
            }
        }
#pragma unroll
        for (int q = 0; q < 5; q++) {
            float2 a01 = unpack2(acc[q][0]);
            float2 a23 = unpack2(acc[q][1]);
            float4 o; o.x = a01.x; o.y = a01.y; o.z = a23.x; o.w = a23.y;
            *(float4*)&g_sm[b * 500 + q * 100 + c0] = o;
        }
    }
}

// ---------------------------------------------------------------------------
extern "C" void kernel_launch(void* const* d_in, const int* in_sizes, int n_in,
                              void* d_out, int out_size)
{
    const float* sub_emb = (const float*)d_in[0];
    const float* memory  = (const float*)d_in[1];
    const int*   sub_len = (const int*)d_in[2];
    const float* raw     = (const float*)d_in[3];
    const float* W_mem   = (const float*)d_in[4];
    const float* b_mem   = (const float*)d_in[5];
    const float* W_sub   = (const float*)d_in[6];
    const float* b_sub   = (const float*)d_in[7];
    const float* W_gate  = (const float*)d_in[8];
    const float* b_gate  = (const float*)d_in[9];
    float* out = (float*)d_out;
    const int B = in_sizes[2];
    const int rows = B * 5;
    const int tiles = (rows + MT - 1) / MT;

    cudaFuncSetAttribute(gemm_tc<0>, cudaFuncAttributeMaxDynamicSharedMemorySize, GSMEM);
    cudaFuncSetAttribute(gemm_tc<1>, cudaFuncAttributeMaxDynamicSharedMemorySize, GSMEM);
    cudaFuncSetAttribute(gemm_tc<2>, cudaFuncAttributeMaxDynamicSharedMemorySize, GSMEM);

    prep_kernel<<<(11 * 104 * KCH + 255) / 256, 256>>>(W_mem, W_sub, W_gate);
    gemm_tc<0><<<tiles, 256, GSMEM>>>(sub_emb, memory, raw, b_mem, nullptr, rows);
    gemm_tc<1><<<tiles, 256, GSMEM>>>(sub_emb, memory, raw, b_sub, nullptr, rows);
    attn_kernel<<<(B + 7) / 8, 256>>>(memory, sub_len, B);
    gemm_tc<2><<<tiles, 256, GSMEM>>>(sub_emb, memory, raw, b_gate, out, rows);
}

// round 7
// speedup vs baseline: 1.8323x; 1.5182x over previous
#include <cuda_runtime.h>
#include <cuda_bf16.h>
#include <cstdint>

// ---------------------------------------------------------------------------
// Reading_memory R7: mma.sync bf16x3 GEMMs, A fragments loaded register-direct
// from gmem (no A smem), B images double-buffered via cp.async.
//   rows = B*5.  Y = act(X @ W + b), N=100(pad104), K in {100,200,300}
//     stage0: X=memory           -> g_m4 (tanh)
//     stage1: X=cat(se,raw)      -> g_s4 (tanh)
//     attn  : softmax masked; g_sm = att @ memory
//     stage2: X=cat(se,sm,se*sm) -> out (sigmoid gate blend)
// ---------------------------------------------------------------------------

#define B_MAX 65536
#define HID 100
#define MT   128
#define KCH  64
#define ASTB 72                    // B image k-stride (elems)
#define BSPL (104 * ASTB * 2)      // bytes per split  = 14976
#define BCHK (2 * BSPL)            // bytes per chunk (hi+lo) = 29952
typedef unsigned long long ull;
typedef unsigned int uint;

__device__ __align__(16) static float g_m4[B_MAX * 500];
__device__ __align__(16) static float g_s4[B_MAX * 500];
__device__ __align__(16) static float g_sm[B_MAX * 500];
__device__ __align__(16) static __nv_bfloat16 g_Bimg[11][2][104 * ASTB];

__device__ __forceinline__ float sigf(float x) { return 1.0f / (1.0f + __expf(-x)); }

__device__ __forceinline__ ull fma2(ull a, ull b, ull c) {
    ull d;
    asm("fma.rn.f32x2 %0, %1, %2, %3;" : "=l"(d) : "l"(a), "l"(b), "l"(c));
    return d;
}
__device__ __forceinline__ ull pack2(float lo, float hi) {
    ull r;
    asm("mov.b64 %0, {%1, %2};" : "=l"(r) : "r"(__float_as_uint(lo)), "r"(__float_as_uint(hi)));
    return r;
}
__device__ __forceinline__ float2 unpack2(ull v) {
    uint lo, hi;
    asm("mov.b64 {%0, %1}, %2;" : "=r"(lo), "=r"(hi) : "l"(v));
    float2 r; r.x = __uint_as_float(lo); r.y = __uint_as_float(hi);
    return r;
}

// split float2 -> packed bf16x2 hi + lo (residual)
__device__ __forceinline__ void sp2(float2 v, uint& h, uint& l) {
    uint hh;
    asm("cvt.rn.bf16x2.f32 %0, %1, %2;" : "=r"(hh) : "f"(v.y), "f"(v.x));
    float rx = v.x - __uint_as_float(hh << 16);
    float ry = v.y - __uint_as_float(hh & 0xFFFF0000u);
    asm("cvt.rn.bf16x2.f32 %0, %1, %2;" : "=r"(l) : "f"(ry), "f"(rx));
    h = hh;
}

#define LDSM2(d0, d1, addr) \
    asm volatile("ldmatrix.sync.aligned.m8n8.x2.shared.b16 {%0,%1}, [%2];" \
                 : "=r"(d0), "=r"(d1) : "r"(addr))

__device__ __forceinline__ void mma16816(float c[4], uint a0, uint a1, uint a2, uint a3,
                                         uint b0, uint b1) {
    asm volatile(
        "mma.sync.aligned.m16n8k16.row.col.f32.bf16.bf16.f32 "
        "{%0,%1,%2,%3}, {%4,%5,%6,%7}, {%8,%9}, {%0,%1,%2,%3};"
        : "+f"(c[0]), "+f"(c[1]), "+f"(c[2]), "+f"(c[3])
        : "r"(a0), "r"(a1), "r"(a2), "r"(a3), "r"(b0), "r"(b1));
}

__device__ __forceinline__ void cpa16(uint saddr, const void* src) {
    asm volatile("cp.async.cg.shared.global [%0], [%1], 16;" :: "r"(saddr), "l"(src));
}

// ---------------------------------------------------------------------------
__global__ void prep_kernel(const float* __restrict__ Wm,
                            const float* __restrict__ Ws,
                            const float* __restrict__ Wg)
{
    const int idx = blockIdx.x * blockDim.x + threadIdx.x;
    const int PER = 104 * KCH;
    if (idx >= 11 * PER) return;
    const int cidx = idx / PER;
    const int rem = idx - cidx * PER;
    const int n = rem / KCH, k = rem - n * KCH;
    int c, KS;
    const float* W;
    if (cidx < 2)      { W = Wm; c = cidx;     KS = 100; }
    else if (cidx < 6) { W = Ws; c = cidx - 2; KS = 200; }
    else               { W = Wg; c = cidx - 6; KS = 300; }
    const int gk = c * KCH + k;
    float v = (n < HID && gk < KS) ? W[gk * HID + n] : 0.0f;
    __nv_bfloat16 hi = __float2bfloat16(v);
    __nv_bfloat16 lo = __float2bfloat16(v - __bfloat162float(hi));
    g_Bimg[cidx][0][n * ASTB + k] = hi;
    g_Bimg[cidx][1][n * ASTB + k] = lo;
}

// ---------------------------------------------------------------------------
// gemm: 256 thr / 8 warps; warp w owns rows [w*16, w*16+16), all 13 n-tiles.
// SMEM: B double buffer 2 x BCHK, then bias.
// ---------------------------------------------------------------------------
#define OFF_BIAS (2 * BCHK)
#define GSMEM (OFF_BIAS + 104 * 4)

template <int STAGE>
__device__ __forceinline__ float2 ldx(const float* __restrict__ se,
                                      const float* __restrict__ mem,
                                      const float* __restrict__ raw,
                                      int grow, int k, int rows)
{
    constexpr int KS = (STAGE == 0) ? 100 : (STAGE == 1 ? 200 : 300);
    float2 z = make_float2(0.f, 0.f);
    if (grow >= rows || k >= KS) return z;
    if (STAGE == 0) return *(const float2*)&mem[grow * HID + k];
    if (STAGE == 1) {
        return (k < HID) ? *(const float2*)&se[grow * HID + k]
                         : *(const float2*)&raw[grow * HID + k - HID];
    }
    if (k < HID)     return *(const float2*)&se[grow * HID + k];
    if (k < 2 * HID) return *(const float2*)&g_sm[grow * HID + k - HID];
    {
        float2 a = *(const float2*)&se[grow * HID + k - 2 * HID];
        float2 b = *(const float2*)&g_sm[grow * HID + k - 2 * HID];
        return make_float2(a.x * b.x, a.y * b.y);
    }
}

template <int STAGE>
__global__ __launch_bounds__(256, 2)
void gemm_tc(const float* __restrict__ se,
             const float* __restrict__ mem,
             const float* __restrict__ raw,
             const float* __restrict__ bias,
             float* __restrict__ dout,
             int rows)
{
    constexpr int NC = (STAGE == 0) ? 2 : (STAGE == 1 ? 4 : 5);
    constexpr int CBASE = (STAGE == 0) ? 0 : (STAGE == 1 ? 2 : 6);
    extern __shared__ __align__(16) char smc[];
    float* bias_s = (float*)(smc + OFF_BIAS);
    const uint smb = (uint)__cvta_generic_to_shared(smc);
    const int tid = threadIdx.x;
    const int wid = tid >> 5;
    const int lane = tid & 31;
    const int row0 = blockIdx.x * MT;

    if (tid < 104) bias_s[tid] = (tid < HID) ? bias[tid] : 0.0f;

    float acc[13][4];
#pragma unroll
    for (int nt = 0; nt < 13; nt++)
#pragma unroll
        for (int j = 0; j < 4; j++) acc[nt][j] = 0.0f;

    const uint boff = (uint)(((lane & 7) * ASTB + ((lane >> 3) & 1) * 8) * 2);
    const char* bsrc = (const char*)&g_Bimg[CBASE][0][0];

    // prefetch B chunk 0 -> buf 0
#pragma unroll
    for (int it = 0; it < 8; it++) {
        int idx = tid + it * 256;
        if (idx < BCHK / 16) cpa16(smb + (uint)(idx * 16), bsrc + idx * 16);
    }
    asm volatile("cp.async.commit_group;");

    const int r_lo = row0 + wid * 16 + (lane >> 2);
    const int r_hi = r_lo + 8;
    int buf = 0;

    for (int c = 0; c < NC; c++) {
        if (c + 1 < NC) {
            const char* src = bsrc + (c + 1) * BCHK;
            const uint dst = smb + (uint)((buf ^ 1) * BCHK);
#pragma unroll
            for (int it = 0; it < 8; it++) {
                int idx = tid + it * 256;
                if (idx < BCHK / 16) cpa16(dst + (uint)(idx * 16), src + idx * 16);
            }
            asm volatile("cp.async.commit_group;");
            asm volatile("cp.async.wait_group 1;" ::: "memory");
        } else {
            asm volatile("cp.async.wait_group 0;" ::: "memory");
        }
        __syncthreads();     // B[buf] visible to all warps

        const uint bH = smb + (uint)(buf * BCHK) + boff;
        const uint bL = bH + BSPL;

#pragma unroll
        for (int ks = 0; ks < 4; ks++) {
            const int kb = c * KCH + ks * 16 + (lane & 3) * 2;
            float2 x0 = ldx<STAGE>(se, mem, raw, r_lo, kb,     rows);
            float2 x1 = ldx<STAGE>(se, mem, raw, r_lo, kb + 8, rows);
            float2 x2 = ldx<STAGE>(se, mem, raw, r_hi, kb,     rows);
            float2 x3 = ldx<STAGE>(se, mem, raw, r_hi, kb + 8, rows);
            uint ah0, ah1, ah2, ah3, al0, al1, al2, al3;
            sp2(x0, ah0, al0);
            sp2(x2, ah1, al1);
            sp2(x1, ah2, al2);
            sp2(x3, ah3, al3);
#pragma unroll
            for (int nt = 0; nt < 13; nt++) {
                uint bh0, bh1, bl0, bl1;
                const uint nb = (uint)(nt * 8 * ASTB * 2 + ks * 32);
                LDSM2(bh0, bh1, bH + nb);
                LDSM2(bl0, bl1, bL + nb);
                mma16816(acc[nt], ah0, ah1, ah2, ah3, bh0, bh1);
                mma16816(acc[nt], ah0, ah1, ah2, ah3, bl0, bl1);
                mma16816(acc[nt], al0, al1, al2, al3, bh0, bh1);
            }
        }
        __syncthreads();     // all warps done with buf before it is refilled
        buf ^= 1;
    }

    // ---- epilogue ----
    const int g = lane >> 2, tg = lane & 3;
    const int r0 = row0 + wid * 16 + g;
    const int r1 = r0 + 8;
#pragma unroll
    for (int nt = 0; nt < 13; nt++) {
        const int n0 = nt * 8 + tg * 2;
        if (n0 >= HID) continue;
        const float bz0 = bias_s[n0], bz1 = bias_s[n0 + 1];
#pragma unroll
        for (int half = 0; half < 2; half++) {
            const int rr = half ? r1 : r0;
            if (rr >= rows) continue;
            float z0 = acc[nt][half * 2]     + bz0;
            float z1 = acc[nt][half * 2 + 1] + bz1;
            const int off = rr * HID + n0;
            float2 o;
            if (STAGE < 2) {
                o.x = tanhf(z0); o.y = tanhf(z1);
                float* dst = (STAGE == 0) ? g_m4 : g_s4;
                *(float2*)&dst[off] = o;
            } else {
                float2 sev = *(const float2*)&se[off];
                float2 smv = *(const float2*)&g_sm[off];
                o.x = fmaf(sigf(z0), smv.x - sev.x, sev.x);
                o.y = fmaf(sigf(z1), smv.y - sev.y, sev.y);
                *(float2*)&dout[off] = o;
            }
        }
    }
}

// ---------------------------------------------------------------------------
// Attention kernel (known-good): one warp per batch, 8 per CTA.
// ---------------------------------------------------------------------------
__global__ __launch_bounds__(256)
void attn_kernel(const float* __restrict__ memory,
                 const int* __restrict__ sub_len,
                 int B)
{
    __shared__ __align__(16) float s4s[8][500];
    __shared__ __align__(16) float m4s[8][500];
    __shared__ float atts[8][25];
    __shared__ __align__(16) ull attd[8][25];

    const int w = threadIdx.x >> 5;
    const int lane = threadIdx.x & 31;
    const int b = blockIdx.x * 8 + w;
    if (b >= B) return;

    for (int i = lane; i < 125; i += 32) {
        *(float4*)&s4s[w][4 * i] = *(const float4*)&g_s4[b * 500 + 4 * i];
        *(float4*)&m4s[w][4 * i] = *(const float4*)&g_m4[b * 500 + 4 * i];
    }
    __syncwarp();

    if (lane < 25) {
        const int q = lane / 5, kk = lane % 5;
        float a = 0.0f;
#pragma unroll 4
        for (int h = 0; h < 100; h++)
            a += s4s[w][q * 100 + h] * m4s[w][kk * 100 + h];
        atts[w][lane] = a;
    }
    __syncwarp();

    if (lane < 5) {
        const int q = lane;
        const int len = sub_len[b];
        float a[5];
#pragma unroll
        for (int i = 0; i < 5; i++) a[i] = atts[w][q * 5 + i];
        float m = a[0];
#pragma unroll
        for (int i = 1; i < 5; i++) m = fmaxf(m, a[i]);
        float e[5], s = 0.0f;
#pragma unroll
        for (int i = 0; i < 5; i++) { e[i] = __expf(a[i] - m); s += e[i]; }
        const float inv = (q < len) ? (1.0f / s) : 0.0f;
#pragma unroll
        for (int i = 0; i < 5; i++) {
            float r = e[i] * inv;
            attd[w][q * 5 + i] = pack2(r, r);
        }
    }
    __syncwarp();

    if (lane < 25) {
        const int c0 = 4 * lane;
        ull acc[5][2];
#pragma unroll
        for (int q = 0; q < 5; q++) { acc[q][0] = 0ull; acc[q][1] = 0ull; }
#pragma unroll
        for (int kk = 0; kk < 5; kk++) {
            ulonglong2 mv = *(const ulonglong2*)&memory[b * 500 + kk * 100 + c0];
#pragma unroll
            for (int q = 0; q < 5; q++) {
                ull ad = attd[w][q * 5 + kk];
                acc[q][0] = fma2(ad, mv.x, acc[q][0]);
                acc[q][1] = fma2(ad, mv.y, acc[q][1]);
            }
        }
#pragma unroll
        for (int q = 0; q < 5; q++) {
            float2 a01 = unpack2(acc[q][0]);
            float2 a23 = unpack2(acc[q][1]);
            float4 o; o.x = a01.x; o.y = a01.y; o.z = a23.x; o.w = a23.y;
            *(float4*)&g_sm[b * 500 + q * 100 + c0] = o;
        }
    }
}

// ---------------------------------------------------------------------------
extern "C" void kernel_launch(void* const* d_in, const int* in_sizes, int n_in,
                              void* d_out, int out_size)
{
    const float* sub_emb = (const float*)d_in[0];
    const float* memory  = (const float*)d_in[1];
    const int*   sub_len = (const int*)d_in[2];
    const float* raw     = (const float*)d_in[3];
    const float* W_mem   = (const float*)d_in[4];
    const float* b_mem   = (const float*)d_in[5];
    const float* W_sub   = (const float*)d_in[6];
    const float* b_sub   = (const float*)d_in[7];
    const float* W_gate  = (const float*)d_in[8];
    const float* b_gate  = (const float*)d_in[9];
    float* out = (float*)d_out;
    const int B = in_sizes[2];
    const int rows = B * 5;
    const int tiles = (rows + MT - 1) / MT;

    cudaFuncSetAttribute(gemm_tc<0>, cudaFuncAttributeMaxDynamicSharedMemorySize, GSMEM);
    cudaFuncSetAttribute(gemm_tc<1>, cudaFuncAttributeMaxDynamicSharedMemorySize, GSMEM);
    cudaFuncSetAttribute(gemm_tc<2>, cudaFuncAttributeMaxDynamicSharedMemorySize, GSMEM);

    prep_kernel<<<(11 * 104 * KCH + 255) / 256, 256>>>(W_mem, W_sub, W_gate);
    gemm_tc<0><<<tiles, 256, GSMEM>>>(sub_emb, memory, raw, b_mem, nullptr, rows);
    gemm_tc<1><<<tiles, 256, GSMEM>>>(sub_emb, memory, raw, b_sub, nullptr, rows);
    attn_kernel<<<(B + 7) / 8, 256>>>(memory, sub_len, B);
    gemm_tc<2><<<tiles, 256, GSMEM>>>(sub_emb, memory, raw, b_gate, out, rows);
}

// round 8
// speedup vs baseline: 1.8910x; 1.0320x over previous
#include <cuda_runtime.h>
#include <cuda_bf16.h>
#include <cstdint>

// ---------------------------------------------------------------------------
// Reading_memory R8: mma.sync bf16x3 GEMMs; A register-direct from gmem,
// B double-buffered cp.async with ldmatrix.x4 paired n-tiles.
// stage0+1 merged in one launch (grid.y), attention LDS.128 score loop.
// ---------------------------------------------------------------------------

#define B_MAX 65536
#define HID 100
#define MT   128
#define KCH  64
#define ASTB 72                    // B image k-stride (elems)
#define BSPL (104 * ASTB * 2)      // bytes per split  = 14976
#define BCHK (2 * BSPL)            // bytes per chunk (hi+lo)
typedef unsigned long long ull;
typedef unsigned int uint;

__device__ __align__(16) static float g_m4[B_MAX * 500];
__device__ __align__(16) static float g_s4[B_MAX * 500];
__device__ __align__(16) static float g_sm[B_MAX * 500];
__device__ __align__(16) static __nv_bfloat16 g_Bimg[11][2][104 * ASTB];

__device__ __forceinline__ float sigf(float x) { return 1.0f / (1.0f + __expf(-x)); }

__device__ __forceinline__ ull fma2(ull a, ull b, ull c) {
    ull d;
    asm("fma.rn.f32x2 %0, %1, %2, %3;" : "=l"(d) : "l"(a), "l"(b), "l"(c));
    return d;
}
__device__ __forceinline__ ull pack2(float lo, float hi) {
    ull r;
    asm("mov.b64 %0, {%1, %2};" : "=l"(r) : "r"(__float_as_uint(lo)), "r"(__float_as_uint(hi)));
    return r;
}
__device__ __forceinline__ float2 unpack2(ull v) {
    uint lo, hi;
    asm("mov.b64 {%0, %1}, %2;" : "=r"(lo), "=r"(hi) : "l"(v));
    float2 r; r.x = __uint_as_float(lo); r.y = __uint_as_float(hi);
    return r;
}
__device__ __forceinline__ void sp2(float2 v, uint& h, uint& l) {
    uint hh;
    asm("cvt.rn.bf16x2.f32 %0, %1, %2;" : "=r"(hh) : "f"(v.y), "f"(v.x));
    float rx = v.x - __uint_as_float(hh << 16);
    float ry = v.y - __uint_as_float(hh & 0xFFFF0000u);
    asm("cvt.rn.bf16x2.f32 %0, %1, %2;" : "=r"(l) : "f"(ry), "f"(rx));
    h = hh;
}

#define LDSM2(d0, d1, addr) \
    asm volatile("ldmatrix.sync.aligned.m8n8.x2.shared.b16 {%0,%1}, [%2];" \
                 : "=r"(d0), "=r"(d1) : "r"(addr))
#define LDSM4(d0, d1, d2, d3, addr) \
    asm volatile("ldmatrix.sync.aligned.m8n8.x4.shared.b16 {%0,%1,%2,%3}, [%4];" \
                 : "=r"(d0), "=r"(d1), "=r"(d2), "=r"(d3) : "r"(addr))

__device__ __forceinline__ void mma16816(float c[4], uint a0, uint a1, uint a2, uint a3,
                                         uint b0, uint b1) {
    asm volatile(
        "mma.sync.aligned.m16n8k16.row.col.f32.bf16.bf16.f32 "
        "{%0,%1,%2,%3}, {%4,%5,%6,%7}, {%8,%9}, {%0,%1,%2,%3};"
        : "+f"(c[0]), "+f"(c[1]), "+f"(c[2]), "+f"(c[3])
        : "r"(a0), "r"(a1), "r"(a2), "r"(a3), "r"(b0), "r"(b1));
}

__device__ __forceinline__ void cpa16(uint saddr, const void* src) {
    asm volatile("cp.async.cg.shared.global [%0], [%1], 16;" :: "r"(saddr), "l"(src));
}

// ---------------------------------------------------------------------------
__global__ void prep_kernel(const float* __restrict__ Wm,
                            const float* __restrict__ Ws,
                            const float* __restrict__ Wg)
{
    const int idx = blockIdx.x * blockDim.x + threadIdx.x;
    const int PER = 104 * KCH;
    if (idx >= 11 * PER) return;
    const int cidx = idx / PER;
    const int rem = idx - cidx * PER;
    const int n = rem / KCH, k = rem - n * KCH;
    int c, KS;
    const float* W;
    if (cidx < 2)      { W = Wm; c = cidx;     KS = 100; }
    else if (cidx < 6) { W = Ws; c = cidx - 2; KS = 200; }
    else               { W = Wg; c = cidx - 6; KS = 300; }
    const int gk = c * KCH + k;
    float v = (n < HID && gk < KS) ? W[gk * HID + n] : 0.0f;
    __nv_bfloat16 hi = __float2bfloat16(v);
    __nv_bfloat16 lo = __float2bfloat16(v - __bfloat162float(hi));
    g_Bimg[cidx][0][n * ASTB + k] = hi;
    g_Bimg[cidx][1][n * ASTB + k] = lo;
}

// ---------------------------------------------------------------------------
#define OFF_BIAS (2 * BCHK)
#define GSMEM (OFF_BIAS + 104 * 4)

template <int STAGE>
__device__ __forceinline__ float2 ldx(const float* __restrict__ se,
                                      const float* __restrict__ mem,
                                      const float* __restrict__ raw,
                                      int grow, int k, int rows)
{
    constexpr int KS = (STAGE == 0) ? 100 : (STAGE == 1 ? 200 : 300);
    float2 z = make_float2(0.f, 0.f);
    if (grow >= rows || k >= KS) return z;
    if (STAGE == 0) return *(const float2*)&mem[grow * HID + k];
    if (STAGE == 1) {
        return (k < HID) ? *(const float2*)&se[grow * HID + k]
                         : *(const float2*)&raw[grow * HID + k - HID];
    }
    if (k < HID)     return *(const float2*)&se[grow * HID + k];
    if (k < 2 * HID) return *(const float2*)&g_sm[grow * HID + k - HID];
    {
        float2 a = *(const float2*)&se[grow * HID + k - 2 * HID];
        float2 b = *(const float2*)&g_sm[grow * HID + k - 2 * HID];
        return make_float2(a.x * b.x, a.y * b.y);
    }
}

template <int STAGE>
__device__ __forceinline__ void gemm_body(const float* __restrict__ se,
                                          const float* __restrict__ mem,
                                          const float* __restrict__ raw,
                                          const float* __restrict__ bias,
                                          float* __restrict__ dout,
                                          int rows)
{
    constexpr int NC = (STAGE == 0) ? 2 : (STAGE == 1 ? 4 : 5);
    constexpr int CBASE = (STAGE == 0) ? 0 : (STAGE == 1 ? 2 : 6);
    extern __shared__ __align__(16) char smc[];
    float* bias_s = (float*)(smc + OFF_BIAS);
    const uint smb = (uint)__cvta_generic_to_shared(smc);
    const int tid = threadIdx.x;
    const int wid = tid >> 5;
    const int lane = tid & 31;
    const int row0 = blockIdx.x * MT;

    if (tid < 104) bias_s[tid] = (tid < HID) ? bias[tid] : 0.0f;

    float acc[13][4];
#pragma unroll
    for (int nt = 0; nt < 13; nt++)
#pragma unroll
        for (int j = 0; j < 4; j++) acc[nt][j] = 0.0f;

    // x2 address (last n-tile), x4 address (n-tile pairs)
    const uint boff2 = (uint)(((lane & 7) * ASTB + ((lane >> 3) & 1) * 8) * 2);
    const uint nrow4 = (uint)((lane & 7) | ((lane >> 1) & 8));
    const uint boff4 = (uint)((nrow4 * ASTB + ((lane >> 3) & 1) * 8) * 2);
    const char* bsrc = (const char*)&g_Bimg[CBASE][0][0];

#pragma unroll
    for (int it = 0; it < 8; it++) {
        int idx = tid + it * 256;
        if (idx < BCHK / 16) cpa16(smb + (uint)(idx * 16), bsrc + idx * 16);
    }
    asm volatile("cp.async.commit_group;");

    const int r_lo = row0 + wid * 16 + (lane >> 2);
    const int r_hi = r_lo + 8;
    int buf = 0;

    for (int c = 0; c < NC; c++) {
        if (c + 1 < NC) {
            const char* src = bsrc + (c + 1) * BCHK;
            const uint dst = smb + (uint)((buf ^ 1) * BCHK);
#pragma unroll
            for (int it = 0; it < 8; it++) {
                int idx = tid + it * 256;
                if (idx < BCHK / 16) cpa16(dst + (uint)(idx * 16), src + idx * 16);
            }
            asm volatile("cp.async.commit_group;");
            asm volatile("cp.async.wait_group 1;" ::: "memory");
        } else {
            asm volatile("cp.async.wait_group 0;" ::: "memory");
        }
        __syncthreads();

        const uint bB = smb + (uint)(buf * BCHK);

#pragma unroll
        for (int ks = 0; ks < 4; ks++) {
            const int kb = c * KCH + ks * 16 + (lane & 3) * 2;
            float2 x0 = ldx<STAGE>(se, mem, raw, r_lo, kb,     rows);
            float2 x1 = ldx<STAGE>(se, mem, raw, r_lo, kb + 8, rows);
            float2 x2 = ldx<STAGE>(se, mem, raw, r_hi, kb,     rows);
            float2 x3 = ldx<STAGE>(se, mem, raw, r_hi, kb + 8, rows);
            uint ah0, ah1, ah2, ah3, al0, al1, al2, al3;
            sp2(x0, ah0, al0);
            sp2(x2, ah1, al1);
            sp2(x1, ah2, al2);
            sp2(x3, ah3, al3);
            const uint kby = (uint)(ks * 32);
#pragma unroll
            for (int np = 0; np < 6; np++) {
                const uint nb = (uint)(np * 16 * ASTB * 2) + kby;
                uint bh0, bh1, bh2, bh3, bl0, bl1, bl2, bl3;
                LDSM4(bh0, bh1, bh2, bh3, bB + boff4 + nb);
                LDSM4(bl0, bl1, bl2, bl3, bB + BSPL + boff4 + nb);
                mma16816(acc[2 * np],     ah0, ah1, ah2, ah3, bh0, bh1);
                mma16816(acc[2 * np],     ah0, ah1, ah2, ah3, bl0, bl1);
                mma16816(acc[2 * np],     al0, al1, al2, al3, bh0, bh1);
                mma16816(acc[2 * np + 1], ah0, ah1, ah2, ah3, bh2, bh3);
                mma16816(acc[2 * np + 1], ah0, ah1, ah2, ah3, bl2, bl3);
                mma16816(acc[2 * np + 1], al0, al1, al2, al3, bh2, bh3);
            }
            {   // last n-tile (nt=12, rows 96..103)
                const uint nb = (uint)(12 * 8 * ASTB * 2) + kby;
                uint bh0, bh1, bl0, bl1;
                LDSM2(bh0, bh1, bB + boff2 + nb);
                LDSM2(bl0, bl1, bB + BSPL + boff2 + nb);
                mma16816(acc[12], ah0, ah1, ah2, ah3, bh0, bh1);
                mma16816(acc[12], ah0, ah1, ah2, ah3, bl0, bl1);
                mma16816(acc[12], al0, al1, al2, al3, bh0, bh1);
            }
        }
        __syncthreads();
        buf ^= 1;
    }

    // ---- epilogue ----
    const int g = lane >> 2, tg = lane & 3;
    const int r0 = row0 + wid * 16 + g;
    const int r1 = r0 + 8;
#pragma unroll
    for (int nt = 0; nt < 13; nt++) {
        const int n0 = nt * 8 + tg * 2;
        if (n0 >= HID) continue;
        const float bz0 = bias_s[n0], bz1 = bias_s[n0 + 1];
#pragma unroll
        for (int half = 0; half < 2; half++) {
            const int rr = half ? r1 : r0;
            if (rr >= rows) continue;
            float z0 = acc[nt][half * 2]     + bz0;
            float z1 = acc[nt][half * 2 + 1] + bz1;
            const int off = rr * HID + n0;
            float2 o;
            if (STAGE < 2) {
                o.x = tanhf(z0); o.y = tanhf(z1);
                float* dst = (STAGE == 0) ? g_m4 : g_s4;
                *(float2*)&dst[off] = o;
            } else {
                float2 sev = *(const float2*)&se[off];
                float2 smv = *(const float2*)&g_sm[off];
                o.x = fmaf(sigf(z0), smv.x - sev.x, sev.x);
                o.y = fmaf(sigf(z1), smv.y - sev.y, sev.y);
                *(float2*)&dout[off] = o;
            }
        }
    }
}

__global__ __launch_bounds__(256, 2)
void gemm01(const float* __restrict__ se, const float* __restrict__ mem,
            const float* __restrict__ raw,
            const float* __restrict__ b_mem, const float* __restrict__ b_sub,
            int rows)
{
    if (blockIdx.y == 0) gemm_body<0>(se, mem, raw, b_mem, nullptr, rows);
    else                 gemm_body<1>(se, mem, raw, b_sub, nullptr, rows);
}

__global__ __launch_bounds__(256, 2)
void gemm2(const float* __restrict__ se, const float* __restrict__ mem,
           const float* __restrict__ raw, const float* __restrict__ b_gate,
           float* __restrict__ dout, int rows)
{
    gemm_body<2>(se, mem, raw, b_gate, dout, rows);
}

// ---------------------------------------------------------------------------
// Attention: one warp per batch, 8 per CTA; LDS.128 score loop.
// ---------------------------------------------------------------------------
__global__ __launch_bounds__(256)
void attn_kernel(const float* __restrict__ memory,
                 const int* __restrict__ sub_len,
                 int B)
{
    __shared__ __align__(16) float s4s[8][500];
    __shared__ __align__(16) float m4s[8][500];
    __shared__ float atts[8][25];
    __shared__ __align__(16) ull attd[8][25];

    const int w = threadIdx.x >> 5;
    const int lane = threadIdx.x & 31;
    const int b = blockIdx.x * 8 + w;
    if (b >= B) return;

    for (int i = lane; i < 125; i += 32) {
        *(float4*)&s4s[w][4 * i] = *(const float4*)&g_s4[b * 500 + 4 * i];
        *(float4*)&m4s[w][4 * i] = *(const float4*)&g_m4[b * 500 + 4 * i];
    }
    __syncwarp();

    if (lane < 25) {
        const int q = lane / 5, kk = lane % 5;
        float a = 0.0f;
#pragma unroll
        for (int j = 0; j < 25; j++) {
            float4 sv = *(const float4*)&s4s[w][q * 100 + 4 * j];
            float4 mv = *(const float4*)&m4s[w][kk * 100 + 4 * j];
            a += sv.x * mv.x + sv.y * mv.y + sv.z * mv.z + sv.w * mv.w;
        }
        atts[w][lane] = a;
    }
    __syncwarp();

    if (lane < 5) {
        const int q = lane;
        const int len = sub_len[b];
        float a[5];
#pragma unroll
        for (int i = 0; i < 5; i++) a[i] = atts[w][q * 5 + i];
        float m = a[0];
#pragma unroll
        for (int i = 1; i < 5; i++) m = fmaxf(m, a[i]);
        float e[5], s = 0.0f;
#pragma unroll
        for (int i = 0; i < 5; i++) { e[i] = __expf(a[i] - m); s += e[i]; }
        const float inv = (q < len) ? (1.0f / s) : 0.0f;
#pragma unroll
        for (int i = 0; i < 5; i++) {
            float r = e[i] * inv;
            attd[w][q * 5 + i] = pack2(r, r);
        }
    }
    __syncwarp();

    if (lane < 25) {
        const int c0 = 4 * lane;
        ull acc[5][2];
#pragma unroll
        for (int q = 0; q < 5; q++) { acc[q][0] = 0ull; acc[q][1] = 0ull; }
#pragma unroll
        for (int kk = 0; kk < 5; kk++) {
            ulonglong2 mv = *(const ulonglong2*)&memory[b * 500 + kk * 100 + c0];
#pragma unroll
            for (int q = 0; q < 5; q++) {
                ull ad = attd[w][q * 5 + kk];
                acc[q][0] = fma2(ad, mv.x, acc[q][0]);
                acc[q][1] = fma2(ad, mv.y, acc[q][1]);
            }
        }
#pragma unroll
        for (int q = 0; q < 5; q++) {
            float2 a01 = unpack2(acc[q][0]);
            float2 a23 = unpack2(acc[q][1]);
            float4 o; o.x = a01.x; o.y = a01.y; o.z = a23.x; o.w = a23.y;
            *(float4*)&g_sm[b * 500 + q * 100 + c0] = o;
        }
    }
}

// ---------------------------------------------------------------------------
extern "C" void kernel_launch(void* const* d_in, const int* in_sizes, int n_in,
                              void* d_out, int out_size)
{
    const float* sub_emb = (const float*)d_in[0];
    const float* memory  = (const float*)d_in[1];
    const int*   sub_len = (const int*)d_in[2];
    const float* raw     = (const float*)d_in[3];
    const float* W_mem   = (const float*)d_in[4];
    const float* b_mem   = (const float*)d_in[5];
    const float* W_sub   = (const float*)d_in[6];
    const float* b_sub   = (const float*)d_in[7];
    const float* W_gate  = (const float*)d_in[8];
    const float* b_gate  = (const float*)d_in[9];
    float* out = (float*)d_out;
    const int B = in_sizes[2];
    const int rows = B * 5;
    const int tiles = (rows + MT - 1) / MT;

    cudaFuncSetAttribute(gemm01, cudaFuncAttributeMaxDynamicSharedMemorySize, GSMEM);
    cudaFuncSetAttribute(gemm2,  cudaFuncAttributeMaxDynamicSharedMemorySize, GSMEM);

    prep_kernel<<<(11 * 104 * KCH + 255) / 256, 256>>>(W_mem, W_sub, W_gate);
    gemm01<<<dim3(tiles, 2), 256, GSMEM>>>(sub_emb, memory, raw, b_mem, b_sub, rows);
    attn_kernel<<<(B + 7) / 8, 256>>>(memory, sub_len, B);
    gemm2<<<tiles, 256, GSMEM>>>(sub_emb, memory, raw, b_gate, out, rows);
}